// round 1
// baseline (speedup 1.0000x reference)
#include <cuda_runtime.h>
#include <cstdint>
#include <cstddef>

#define B_   1024
#define S_   100
#define H_   512
#define G3   1536
#define NU   1000

// ---------------- scratch (static device memory; no allocations) ----------------
__device__ float g_xproj[(size_t)B_ * S_ * G3];   // [B,S,3H]  ~629 MB
__device__ float g_out[(size_t)B_ * S_ * H_];     // [B,S,H]   ~210 MB
__device__ float g_h[2][B_ * H_];                 // ping-pong hidden state
__device__ float g_R[NU * H_];                    // row-sums of Wa per (user, o)

// ---------------- helpers ----------------
__device__ __forceinline__ float tf32r(float x) {
    uint32_t u;
    asm("cvt.rna.tf32.f32 %0, %1;" : "=r"(u) : "f"(x));
    return __uint_as_float(u);
}

__device__ __forceinline__ void mma8(float c[4], const uint32_t a[4], const uint32_t b[2]) {
    asm volatile(
        "mma.sync.aligned.m16n8k8.row.col.f32.tf32.tf32.f32 "
        "{%0,%1,%2,%3}, {%4,%5,%6,%7}, {%8,%9}, {%0,%1,%2,%3};\n"
        : "+f"(c[0]), "+f"(c[1]), "+f"(c[2]), "+f"(c[3])
        : "r"(a[0]), "r"(a[1]), "r"(a[2]), "r"(a[3]), "r"(b[0]), "r"(b[1]));
}

__device__ __forceinline__ float sigmoidf_(float x) { return 1.0f / (1.0f + expf(-x)); }

#define KC 32
#define SPAD 4   // smem stride pad -> stride 36 words, conflict-free fragment loads

// =====================================================================
// Kernel 1: x_proj = X[102400,512] @ W_ih[1536,512]^T + b_ih
// CTA tile 128x64, warp tile 32x32 (warps 4x2), 256 threads
// =====================================================================
__global__ void xproj_kernel(const float* __restrict__ X,
                             const float* __restrict__ Wih,
                             const float* __restrict__ bih) {
    __shared__ float As[128][KC + SPAD];
    __shared__ float Bs[64][KC + SPAD];

    const int m0 = blockIdx.x * 128;
    const int n0 = blockIdx.y * 64;
    const int tid  = threadIdx.x;
    const int lane = tid & 31;
    const int w    = tid >> 5;
    const int g    = lane >> 2;
    const int t4   = lane & 3;
    const int wm = (w >> 1) * 32;
    const int wn = (w & 1) * 32;

    float c[2][4][4];
#pragma unroll
    for (int i = 0; i < 2; i++)
#pragma unroll
        for (int j = 0; j < 4; j++)
#pragma unroll
            for (int k = 0; k < 4; k++) c[i][j][k] = 0.0f;

    for (int kc = 0; kc < 512; kc += KC) {
#pragma unroll
        for (int i = 0; i < 4; i++) {           // A: 128 rows x 32 cols
            int lin = tid + i * 256;
            int row = lin >> 3, c4 = (lin & 7) * 4;
            float4 v = *(const float4*)&X[(size_t)(m0 + row) * 512 + kc + c4];
            As[row][c4 + 0] = tf32r(v.x); As[row][c4 + 1] = tf32r(v.y);
            As[row][c4 + 2] = tf32r(v.z); As[row][c4 + 3] = tf32r(v.w);
        }
#pragma unroll
        for (int i = 0; i < 2; i++) {           // B: 64 rows x 32 cols
            int lin = tid + i * 256;
            int row = lin >> 3, c4 = (lin & 7) * 4;
            float4 v = *(const float4*)&Wih[(size_t)(n0 + row) * 512 + kc + c4];
            Bs[row][c4 + 0] = tf32r(v.x); Bs[row][c4 + 1] = tf32r(v.y);
            Bs[row][c4 + 2] = tf32r(v.z); Bs[row][c4 + 3] = tf32r(v.w);
        }
        __syncthreads();
#pragma unroll
        for (int kk = 0; kk < KC; kk += 8) {
            uint32_t a[2][4], b[4][2];
#pragma unroll
            for (int mt = 0; mt < 2; mt++) {
                int rb = wm + mt * 16;
                a[mt][0] = __float_as_uint(As[rb + g    ][kk + t4]);
                a[mt][1] = __float_as_uint(As[rb + g + 8][kk + t4]);
                a[mt][2] = __float_as_uint(As[rb + g    ][kk + 4 + t4]);
                a[mt][3] = __float_as_uint(As[rb + g + 8][kk + 4 + t4]);
            }
#pragma unroll
            for (int nt = 0; nt < 4; nt++) {
                int nb = wn + nt * 8 + g;
                b[nt][0] = __float_as_uint(Bs[nb][kk + t4]);
                b[nt][1] = __float_as_uint(Bs[nb][kk + 4 + t4]);
            }
#pragma unroll
            for (int mt = 0; mt < 2; mt++)
#pragma unroll
                for (int nt = 0; nt < 4; nt++) mma8(c[mt][nt], a[mt], b[nt]);
        }
        __syncthreads();
    }
    // epilogue: + b_ih, write
#pragma unroll
    for (int mt = 0; mt < 2; mt++) {
#pragma unroll
        for (int nt = 0; nt < 4; nt++) {
            int row = m0 + wm + mt * 16 + g;
            int col = n0 + wn + nt * 8 + 2 * t4;
            float b0 = bih[col], b1 = bih[col + 1];
            float2 v0 = make_float2(c[mt][nt][0] + b0, c[mt][nt][1] + b1);
            float2 v1 = make_float2(c[mt][nt][2] + b0, c[mt][nt][3] + b1);
            *(float2*)&g_xproj[(size_t)row * G3 + col]       = v0;
            *(float2*)&g_xproj[(size_t)(row + 8) * G3 + col] = v1;
        }
    }
}

// =====================================================================
// Kernel 2: one GRU step (fused gh-GEMM + gates)
// CTA: 64 batch rows x 32 h-cols (gathers W_hh rows {j, 512+j, 1024+j})
// warp tile 16x48 (warps 4x2), 256 threads
// =====================================================================
__global__ void gru_step_kernel(const float* __restrict__ hidden_init,
                                const float* __restrict__ Whh,
                                const float* __restrict__ bhh,
                                const float* __restrict__ /*unused*/ xp_unused,
                                int t) {
    __shared__ union {
        struct { float A[64][KC + SPAD]; float B[96][KC + SPAD]; } ab;
        float gh[64][97];
    } sm;

    const float* hsrc = (t == 0) ? hidden_init : g_h[(t - 1) & 1];
    float*       hdst = g_h[t & 1];

    const int b0   = blockIdx.x * 64;
    const int col0 = blockIdx.y * 32;
    const int tid  = threadIdx.x;
    const int lane = tid & 31;
    const int w    = tid >> 5;
    const int g    = lane >> 2;
    const int t4   = lane & 3;
    const int wm = (w >> 1) * 16;
    const int wn = (w & 1) * 48;

    float c[6][4];
#pragma unroll
    for (int i = 0; i < 6; i++)
#pragma unroll
        for (int j = 0; j < 4; j++) c[i][j] = 0.0f;

    for (int kc = 0; kc < 512; kc += KC) {
#pragma unroll
        for (int i = 0; i < 2; i++) {           // A: h rows
            int lin = tid + i * 256;
            int row = lin >> 3, c4 = (lin & 7) * 4;
            float4 v = *(const float4*)&hsrc[(size_t)(b0 + row) * 512 + kc + c4];
            sm.ab.A[row][c4 + 0] = tf32r(v.x); sm.ab.A[row][c4 + 1] = tf32r(v.y);
            sm.ab.A[row][c4 + 2] = tf32r(v.z); sm.ab.A[row][c4 + 3] = tf32r(v.w);
        }
#pragma unroll
        for (int i = 0; i < 3; i++) {           // B: gathered W_hh rows (3 gates x 32 cols)
            int lin = tid + i * 256;
            int lr = lin >> 3, c4 = (lin & 7) * 4;
            int grow = (lr >> 5) * 512 + col0 + (lr & 31);
            float4 v = *(const float4*)&Whh[(size_t)grow * 512 + kc + c4];
            sm.ab.B[lr][c4 + 0] = tf32r(v.x); sm.ab.B[lr][c4 + 1] = tf32r(v.y);
            sm.ab.B[lr][c4 + 2] = tf32r(v.z); sm.ab.B[lr][c4 + 3] = tf32r(v.w);
        }
        __syncthreads();
#pragma unroll
        for (int kk = 0; kk < KC; kk += 8) {
            uint32_t a[4], b[6][2];
            a[0] = __float_as_uint(sm.ab.A[wm + g    ][kk + t4]);
            a[1] = __float_as_uint(sm.ab.A[wm + g + 8][kk + t4]);
            a[2] = __float_as_uint(sm.ab.A[wm + g    ][kk + 4 + t4]);
            a[3] = __float_as_uint(sm.ab.A[wm + g + 8][kk + 4 + t4]);
#pragma unroll
            for (int nt = 0; nt < 6; nt++) {
                int nb = wn + nt * 8 + g;
                b[nt][0] = __float_as_uint(sm.ab.B[nb][kk + t4]);
                b[nt][1] = __float_as_uint(sm.ab.B[nb][kk + 4 + t4]);
            }
#pragma unroll
            for (int nt = 0; nt < 6; nt++) mma8(c[nt], a, b[nt]);
        }
        __syncthreads();
    }

    // write fragments into smem gate buffer (aliases the operand tiles)
#pragma unroll
    for (int nt = 0; nt < 6; nt++) {
        int col = wn + nt * 8 + 2 * t4;
        sm.gh[wm + g    ][col]     = c[nt][0];
        sm.gh[wm + g    ][col + 1] = c[nt][1];
        sm.gh[wm + g + 8][col]     = c[nt][2];
        sm.gh[wm + g + 8][col + 1] = c[nt][3];
    }
    __syncthreads();

    // gates: 64 rows x 32 cols = 2048 elements, 8 per thread
#pragma unroll
    for (int i = 0; i < 8; i++) {
        int lin = tid + i * 256;
        int row = lin >> 5, j = lin & 31;
        int bb = b0 + row;
        int jc = col0 + j;
        float gr = sm.gh[row][j]      + bhh[jc];
        float gz = sm.gh[row][32 + j] + bhh[512 + jc];
        float gn = sm.gh[row][64 + j] + bhh[1024 + jc];
        size_t xbase = ((size_t)bb * S_ + t) * G3 + jc;
        float xr = g_xproj[xbase];
        float xz = g_xproj[xbase + 512];
        float xn = g_xproj[xbase + 1024];
        float hprev = hsrc[(size_t)bb * 512 + jc];
        float r  = sigmoidf_(xr + gr);
        float z  = sigmoidf_(xz + gz);
        float nn = tanhf(xn + r * gn);
        float hnew = (1.0f - z) * nn + z * hprev;
        hdst[(size_t)bb * 512 + jc] = hnew;
        g_out[((size_t)bb * S_ + t) * 512 + jc] = hnew;
    }
}

// =====================================================================
// Kernel 3: R[u,o] = sum_h Wa[u,o,h]   (fp32, deterministic)
// =====================================================================
__global__ void r_kernel(const float* __restrict__ Wa) {
    int u = blockIdx.x;
    int w = threadIdx.x >> 5, lane = threadIdx.x & 31;
    for (int o = w; o < 512; o += 8) {
        const float* row = Wa + ((size_t)u * 512 + o) * 512;
        float s = 0.0f;
        for (int h = lane; h < 512; h += 32) s += row[h];
#pragma unroll
        for (int off = 16; off > 0; off >>= 1) s += __shfl_xor_sync(0xffffffffu, s, off);
        if (lane == 0) g_R[u * 512 + o] = s;
    }
}

// =====================================================================
// Kernel 4: per-batch attention: scores -> softmax -> weighted sum
// One CTA per batch row; M=128 (100 valid), loops over 8 o-tiles of 64.
// Masked rows use quantized h~ and bias C[o]=ba[o]-1e6*R[o]  (precision trick).
// =====================================================================
__global__ void attn_kernel(const float* __restrict__ reps,
                            const int*   __restrict__ counts,
                            const int*   __restrict__ users,
                            const float* __restrict__ Wa,
                            const float* __restrict__ ba,
                            const float* __restrict__ Ws,
                            const float* __restrict__ bs,
                            float*       __restrict__ outp) {
    __shared__ float As[128][KC + SPAD];
    __shared__ float Bs[64][KC + SPAD];
    __shared__ float scores_s[128];
    __shared__ float wts[S_];
    __shared__ float inv_s;

    const int b   = blockIdx.x;
    const int u   = users[b];
    const int cnt = counts[b];
    const size_t ub = (size_t)u * 512;
    const float* WaU = Wa + (size_t)u * 512 * 512;

    const int tid  = threadIdx.x;
    const int lane = tid & 31;
    const int w    = tid >> 5;
    const int g    = lane >> 2;
    const int t4   = lane & 3;
    const int wm = w * 16;                       // warp owns rows [wm, wm+16)
    const int s0 = wm + g, s1 = wm + g + 8;
    const bool m0q = (s0 >= cnt), m1q = (s1 >= cnt);

    float pr0 = 0.0f, pr1 = 0.0f;

    for (int ot = 0; ot < 8; ot++) {
        const int o0 = ot * 64;
        float c[8][4];
#pragma unroll
        for (int i = 0; i < 8; i++)
#pragma unroll
            for (int j = 0; j < 4; j++) c[i][j] = 0.0f;

        for (int kc = 0; kc < 512; kc += KC) {
#pragma unroll
            for (int i = 0; i < 4; i++) {        // A: masked GRU output rows
                int lin = tid + i * 256;
                int row = lin >> 3, c4 = (lin & 7) * 4;
                float4 v = make_float4(0.f, 0.f, 0.f, 0.f);
                if (row < S_)
                    v = *(const float4*)&g_out[((size_t)b * S_ + row) * 512 + kc + c4];
                if (row >= cnt) {                // replicate reference's -1e6 quantization
                    v.x = (v.x - 1e6f) + 1e6f; v.y = (v.y - 1e6f) + 1e6f;
                    v.z = (v.z - 1e6f) + 1e6f; v.w = (v.w - 1e6f) + 1e6f;
                }
                As[row][c4 + 0] = tf32r(v.x); As[row][c4 + 1] = tf32r(v.y);
                As[row][c4 + 2] = tf32r(v.z); As[row][c4 + 3] = tf32r(v.w);
            }
#pragma unroll
            for (int i = 0; i < 2; i++) {        // B: Wa rows for this o-tile
                int lin = tid + i * 256;
                int row = lin >> 3, c4 = (lin & 7) * 4;
                float4 v = *(const float4*)&WaU[(size_t)(o0 + row) * 512 + kc + c4];
                Bs[row][c4 + 0] = tf32r(v.x); Bs[row][c4 + 1] = tf32r(v.y);
                Bs[row][c4 + 2] = tf32r(v.z); Bs[row][c4 + 3] = tf32r(v.w);
            }
            __syncthreads();
#pragma unroll
            for (int kk = 0; kk < KC; kk += 8) {
                uint32_t a[4];
                a[0] = __float_as_uint(As[wm + g    ][kk + t4]);
                a[1] = __float_as_uint(As[wm + g + 8][kk + t4]);
                a[2] = __float_as_uint(As[wm + g    ][kk + 4 + t4]);
                a[3] = __float_as_uint(As[wm + g + 8][kk + 4 + t4]);
#pragma unroll
                for (int nt = 0; nt < 8; nt++) {
                    uint32_t bfr[2];
                    int nb = nt * 8 + g;
                    bfr[0] = __float_as_uint(Bs[nb][kk + t4]);
                    bfr[1] = __float_as_uint(Bs[nb][kk + 4 + t4]);
                    mma8(c[nt], a, bfr);
                }
            }
            __syncthreads();
        }
        // epilogue: e = tanh(acc + bias), accumulate e*Ws into row partials
#pragma unroll
        for (int nt = 0; nt < 8; nt++) {
            int col = o0 + nt * 8 + 2 * t4;
            float baa = ba[ub + col], bab = ba[ub + col + 1];
            float Ca = baa - 1e6f * g_R[ub + col];
            float Cb = bab - 1e6f * g_R[ub + col + 1];
            float wsa = Ws[ub + col], wsb = Ws[ub + col + 1];
            pr0 += tanhf(c[nt][0] + (m0q ? Ca : baa)) * wsa
                 + tanhf(c[nt][1] + (m0q ? Cb : bab)) * wsb;
            pr1 += tanhf(c[nt][2] + (m1q ? Ca : baa)) * wsa
                 + tanhf(c[nt][3] + (m1q ? Cb : bab)) * wsb;
        }
    }

    // reduce across the quad (lanes sharing a row)
    pr0 += __shfl_xor_sync(0xffffffffu, pr0, 1);
    pr0 += __shfl_xor_sync(0xffffffffu, pr0, 2);
    pr1 += __shfl_xor_sync(0xffffffffu, pr1, 1);
    pr1 += __shfl_xor_sync(0xffffffffu, pr1, 2);
    float bsu = bs[u];
    if (t4 == 0) {
        if (s0 < S_) scores_s[s0] = pr0 + bsu;
        if (s1 < S_) scores_s[s1] = pr1 + bsu;
    }
    __syncthreads();

    // softmax over s in [0,100)  (warp 0)
    if (w == 0) {
        float m = -1e30f;
        for (int s = lane; s < S_; s += 32) m = fmaxf(m, scores_s[s]);
#pragma unroll
        for (int off = 16; off > 0; off >>= 1) m = fmaxf(m, __shfl_xor_sync(0xffffffffu, m, off));
        float sum = 0.0f;
        for (int s = lane; s < S_; s += 32) {
            float e = expf(scores_s[s] - m);
            wts[s] = e;
            sum += e;
        }
#pragma unroll
        for (int off = 16; off > 0; off >>= 1) sum += __shfl_xor_sync(0xffffffffu, sum, off);
        if (lane == 0) inv_s = 1.0f / sum;
    }
    __syncthreads();

    // user_repr[b,:] = sum_s w_s * reps[b,s,:]
    const float* rb = reps + (size_t)b * S_ * 512;
    float acc0 = 0.0f, acc1 = 0.0f;
    for (int s = 0; s < S_; s++) {
        float wv = wts[s];
        acc0 += wv * rb[(size_t)s * 512 + tid];
        acc1 += wv * rb[(size_t)s * 512 + 256 + tid];
    }
    float inv = inv_s;
    outp[(size_t)b * 512 + tid]       = acc0 * inv;
    outp[(size_t)b * 512 + 256 + tid] = acc1 * inv;
}

// =====================================================================
extern "C" void kernel_launch(void* const* d_in, const int* in_sizes, int n_in,
                              void* d_out, int out_size) {
    (void)in_sizes; (void)n_in; (void)out_size;
    const float* reps   = (const float*)d_in[0];
    const float* hidden = (const float*)d_in[1];
    const int*   counts = (const int*)  d_in[2];
    const int*   users  = (const int*)  d_in[3];
    const float* Wih    = (const float*)d_in[4];
    const float* Whh    = (const float*)d_in[5];
    const float* bih    = (const float*)d_in[6];
    const float* bhh    = (const float*)d_in[7];
    const float* Wa     = (const float*)d_in[8];
    const float* ba     = (const float*)d_in[9];
    const float* Wsc    = (const float*)d_in[10];
    const float* bsc    = (const float*)d_in[11];
    float* outp = (float*)d_out;

    xproj_kernel<<<dim3(800, 24), 256>>>(reps, Wih, bih);
    r_kernel<<<NU, 256>>>(Wa);
    for (int t = 0; t < S_; t++)
        gru_step_kernel<<<dim3(16, 16), 256>>>(hidden, Whh, bhh, nullptr, t);
    attn_kernel<<<B_, 256>>>(reps, counts, users, Wa, ba, Wsc, bsc, outp);
}

// round 2
// speedup vs baseline: 1.3743x; 1.3743x over previous
#include <cuda_runtime.h>
#include <cstdint>
#include <cstddef>

#define B_   1024
#define S_   100
#define H_   512
#define G3   1536
#define NU   1000
#define GRU_CTAS 128

// ---------------- scratch (static device memory; no allocations) ----------------
__device__ float g_xproj[(size_t)B_ * S_ * G3];   // [B,S,3H]
__device__ float g_out[(size_t)B_ * S_ * H_];     // [B,S,H] (h state lives here too)
__device__ unsigned g_bar_count = 0;
__device__ unsigned g_bar_gen   = 0;

// ---------------- helpers ----------------
__device__ __forceinline__ void mma8(float c[4], const uint32_t a[4], const uint32_t b[2]) {
    asm volatile(
        "mma.sync.aligned.m16n8k8.row.col.f32.tf32.tf32.f32 "
        "{%0,%1,%2,%3}, {%4,%5,%6,%7}, {%8,%9}, {%0,%1,%2,%3};\n"
        : "+f"(c[0]), "+f"(c[1]), "+f"(c[2]), "+f"(c[3])
        : "r"(a[0]), "r"(a[1]), "r"(a[2]), "r"(a[3]), "r"(b[0]), "r"(b[1]));
}

__device__ __forceinline__ void cpa16(uint32_t s, const void* g) {
    asm volatile("cp.async.cg.shared.global [%0], [%1], 16;\n" :: "r"(s), "l"(g));
}
__device__ __forceinline__ void cp_commit() { asm volatile("cp.async.commit_group;\n"); }
template<int N> __device__ __forceinline__ void cp_wait() {
    asm volatile("cp.async.wait_group %0;\n" :: "n"(N));
}

__device__ __forceinline__ float sigmoidf_(float x) { return 1.0f / (1.0f + expf(-x)); }
__device__ __forceinline__ uint32_t fasu(float x) { return __float_as_uint(x); }

#define KC 32
#define LDP 36           // padded smem row stride (words)
#define STAGE_F 9216     // floats per pipeline stage (both kernels: 9216)

// =====================================================================
// Kernel 1: x_proj = X[102400,512] @ W_ih[1536,512]^T + b_ih
// CTA tile 128x128, warp tile 32x64 (warps 4x2), cp.async double buffer
// =====================================================================
__global__ void __launch_bounds__(256, 2)
xproj_kernel(const float* __restrict__ X,
             const float* __restrict__ Wih,
             const float* __restrict__ bih) {
    extern __shared__ float sm[];
    const uint32_t smb = (uint32_t)__cvta_generic_to_shared(sm);

    const int m0 = blockIdx.x * 128;
    const int n0 = blockIdx.y * 128;
    const int tid  = threadIdx.x;
    const int lane = tid & 31;
    const int w    = tid >> 5;
    const int g    = lane >> 2;
    const int t4   = lane & 3;
    const int wm = (w >> 1) * 32;
    const int wn = (w & 1) * 64;

    float c[2][8][4];
#pragma unroll
    for (int i = 0; i < 2; i++)
#pragma unroll
        for (int j = 0; j < 8; j++)
#pragma unroll
            for (int k = 0; k < 4; k++) c[i][j][k] = 0.0f;

    const float* pA[4]; const float* pB[4]; uint32_t soA[4], soB[4];
#pragma unroll
    for (int i = 0; i < 4; i++) {
        int lin = tid + i * 256;
        int row = lin >> 3, c4 = (lin & 7) * 4;
        pA[i] = X   + (size_t)(m0 + row) * 512 + c4;
        pB[i] = Wih + (size_t)(n0 + row) * 512 + c4;
        soA[i] = (uint32_t)(row * LDP + c4) * 4u;
        soB[i] = (uint32_t)(4608 + row * LDP + c4) * 4u;
    }

    auto issue = [&](int s, int kc) {
        uint32_t base = smb + (uint32_t)s * (STAGE_F * 4);
#pragma unroll
        for (int i = 0; i < 4; i++) {
            cpa16(base + soA[i], pA[i] + kc);
            cpa16(base + soB[i], pB[i] + kc);
        }
    };

    issue(0, 0); cp_commit();
    for (int it = 0; it < 16; it++) {
        if (it < 15) { issue((it + 1) & 1, (it + 1) * KC); cp_commit(); cp_wait<1>(); }
        else cp_wait<0>();
        __syncthreads();
        const float* A  = sm + (it & 1) * STAGE_F;
        const float* Bs = A + 4608;
#pragma unroll
        for (int kk = 0; kk < KC; kk += 8) {
            uint32_t a[2][4], b[8][2];
#pragma unroll
            for (int mt = 0; mt < 2; mt++) {
                int rb = wm + mt * 16;
                a[mt][0] = fasu(A[(rb + g    ) * LDP + kk + t4]);
                a[mt][1] = fasu(A[(rb + g + 8) * LDP + kk + t4]);
                a[mt][2] = fasu(A[(rb + g    ) * LDP + kk + 4 + t4]);
                a[mt][3] = fasu(A[(rb + g + 8) * LDP + kk + 4 + t4]);
            }
#pragma unroll
            for (int nt = 0; nt < 8; nt++) {
                int nb = wn + nt * 8 + g;
                b[nt][0] = fasu(Bs[nb * LDP + kk + t4]);
                b[nt][1] = fasu(Bs[nb * LDP + kk + 4 + t4]);
            }
#pragma unroll
            for (int mt = 0; mt < 2; mt++)
#pragma unroll
                for (int nt = 0; nt < 8; nt++) mma8(c[mt][nt], a[mt], b[nt]);
        }
        __syncthreads();
    }

#pragma unroll
    for (int mt = 0; mt < 2; mt++) {
#pragma unroll
        for (int nt = 0; nt < 8; nt++) {
            int row = m0 + wm + mt * 16 + g;
            int col = n0 + wn + nt * 8 + 2 * t4;
            float b0 = bih[col], b1 = bih[col + 1];
            float2 v0 = make_float2(c[mt][nt][0] + b0, c[mt][nt][1] + b1);
            float2 v1 = make_float2(c[mt][nt][2] + b0, c[mt][nt][3] + b1);
            *(float2*)&g_xproj[(size_t)row * G3 + col]       = v0;
            *(float2*)&g_xproj[(size_t)(row + 8) * G3 + col] = v1;
        }
    }
}

// =====================================================================
// Grid barrier (sense-reversing generation counter; replay-safe)
// =====================================================================
__device__ __forceinline__ void grid_sync(unsigned nct, unsigned& gen) {
    __syncthreads();
    if (threadIdx.x == 0) {
        unsigned target = gen + 1;
        __threadfence();
        if (atomicAdd(&g_bar_count, 1u) == nct - 1) {
            g_bar_count = 0;
            __threadfence();
            atomicExch(&g_bar_gen, target);
        } else {
            while (*((volatile unsigned*)&g_bar_gen) != target) __nanosleep(64);
            __threadfence();
        }
        gen = target;
    }
    __syncthreads();
}

// =====================================================================
// Kernel 2: persistent GRU — all 100 steps in one launch.
// 128 CTAs (16 batch-tiles x 8 col-tiles), CTA tile 64 batch x 64 hcols
// (=192 gate cols), warp tile 32x48, cp.async double buffer,
// grid barrier between steps. h state ping-pongs inside g_out.
// =====================================================================
__global__ void gru_persist_kernel(const float* __restrict__ hidden,
                                   const float* __restrict__ Whh,
                                   const float* __restrict__ bhh) {
    extern __shared__ float sm[];
    const uint32_t smb = (uint32_t)__cvta_generic_to_shared(sm);

    const int cta  = blockIdx.x;
    const int b0   = (cta >> 3) * 64;
    const int col0 = (cta & 7) * 64;
    const int tid  = threadIdx.x;
    const int lane = tid & 31;
    const int w    = tid >> 5;
    const int g    = lane >> 2;
    const int t4   = lane & 3;
    const int wm = (w >> 2) * 32;
    const int wn = (w & 3) * 48;

    unsigned gen = *((volatile unsigned*)&g_bar_gen);

    // B (gathered W_hh rows) — invariant across steps
    const float* pB[6]; uint32_t soB[6];
#pragma unroll
    for (int i = 0; i < 6; i++) {
        int lin = tid + i * 256;
        int lr = lin >> 3, c4 = (lin & 7) * 4;
        int grow = (lr >> 6) * 512 + col0 + (lr & 63);
        pB[i] = Whh + (size_t)grow * 512 + c4;
        soB[i] = (uint32_t)(2304 + lr * LDP + c4) * 4u;
    }
    int rA[2]; uint32_t soA[2]; int cA4[2];
#pragma unroll
    for (int i = 0; i < 2; i++) {
        int lin = tid + i * 256;
        rA[i] = lin >> 3; cA4[i] = (lin & 7) * 4;
        soA[i] = (uint32_t)(rA[i] * LDP + cA4[i]) * 4u;
    }

    const int erow = tid >> 2;        // 0..63 (epilogue row)
    const int jq   = (tid & 3) * 16;  // 16-col chunk per thread

    for (int t = 0; t < S_; t++) {
        const float* ap[2];
#pragma unroll
        for (int i = 0; i < 2; i++)
            ap[i] = (t == 0)
                  ? hidden + (size_t)(b0 + rA[i]) * 512 + cA4[i]
                  : g_out + ((size_t)(b0 + rA[i]) * S_ + (t - 1)) * 512 + cA4[i];

        auto issue = [&](int s, int kc) {
            uint32_t base = smb + (uint32_t)s * (STAGE_F * 4);
#pragma unroll
            for (int i = 0; i < 2; i++) cpa16(base + soA[i], ap[i] + kc);
#pragma unroll
            for (int i = 0; i < 6; i++) cpa16(base + soB[i], pB[i] + kc);
        };

        float c[2][6][4];
#pragma unroll
        for (int i = 0; i < 2; i++)
#pragma unroll
            for (int j = 0; j < 6; j++)
#pragma unroll
                for (int k = 0; k < 4; k++) c[i][j][k] = 0.0f;

        issue(0, 0); cp_commit();
        for (int it = 0; it < 16; it++) {
            if (it < 15) { issue((it + 1) & 1, (it + 1) * KC); cp_commit(); cp_wait<1>(); }
            else cp_wait<0>();
            __syncthreads();
            const float* A  = sm + (it & 1) * STAGE_F;
            const float* Bs = A + 2304;
#pragma unroll
            for (int kk = 0; kk < KC; kk += 8) {
                uint32_t a[2][4], b[6][2];
#pragma unroll
                for (int mt = 0; mt < 2; mt++) {
                    int rb = wm + mt * 16;
                    a[mt][0] = fasu(A[(rb + g    ) * LDP + kk + t4]);
                    a[mt][1] = fasu(A[(rb + g + 8) * LDP + kk + t4]);
                    a[mt][2] = fasu(A[(rb + g    ) * LDP + kk + 4 + t4]);
                    a[mt][3] = fasu(A[(rb + g + 8) * LDP + kk + 4 + t4]);
                }
#pragma unroll
                for (int nt = 0; nt < 6; nt++) {
                    int nb = wn + nt * 8 + g;
                    b[nt][0] = fasu(Bs[nb * LDP + kk + t4]);
                    b[nt][1] = fasu(Bs[nb * LDP + kk + 4 + t4]);
                }
#pragma unroll
                for (int mt = 0; mt < 2; mt++)
#pragma unroll
                    for (int nt = 0; nt < 6; nt++) mma8(c[mt][nt], a[mt], b[nt]);
            }
            __syncthreads();
        }

        // stage fragments into smem (aliases pipeline buffers; row stride 196)
        float* gh = sm;
#pragma unroll
        for (int mt = 0; mt < 2; mt++) {
#pragma unroll
            for (int nt = 0; nt < 6; nt++) {
                int row = wm + mt * 16 + g;
                int col = wn + nt * 8 + 2 * t4;
                *(float2*)&gh[row * 196 + col]       = make_float2(c[mt][nt][0], c[mt][nt][1]);
                *(float2*)&gh[(row + 8) * 196 + col] = make_float2(c[mt][nt][2], c[mt][nt][3]);
            }
        }
        __syncthreads();

        // gates epilogue: 64x64 outputs, 16 per thread
        {
            int bb = b0 + erow;
            size_t ob = ((size_t)bb * S_ + t) * 512 + col0 + jq;
            size_t xb = ((size_t)bb * S_ + t) * G3 + col0 + jq;
            const float* hp = (t == 0)
                            ? hidden + (size_t)bb * 512 + col0 + jq
                            : g_out + ((size_t)bb * S_ + (t - 1)) * 512 + col0 + jq;
#pragma unroll
            for (int q = 0; q < 4; q++) {
                int j = jq + q * 4;
                float4 gr = *(float4*)&gh[erow * 196 + j];
                float4 gz = *(float4*)&gh[erow * 196 + 64 + j];
                float4 gn = *(float4*)&gh[erow * 196 + 128 + j];
                float4 br = *(const float4*)&bhh[col0 + j];
                float4 bz = *(const float4*)&bhh[512 + col0 + j];
                float4 bn = *(const float4*)&bhh[1024 + col0 + j];
                float4 xr = *(const float4*)&g_xproj[xb + q * 4];
                float4 xz = *(const float4*)&g_xproj[xb + 512 + q * 4];
                float4 xn = *(const float4*)&g_xproj[xb + 1024 + q * 4];
                float4 hv = *(const float4*)&hp[q * 4];
                float4 o;
                {
                    float r = sigmoidf_(xr.x + gr.x + br.x);
                    float z = sigmoidf_(xz.x + gz.x + bz.x);
                    float n = tanhf(xn.x + r * (gn.x + bn.x));
                    o.x = (1.0f - z) * n + z * hv.x;
                }
                {
                    float r = sigmoidf_(xr.y + gr.y + br.y);
                    float z = sigmoidf_(xz.y + gz.y + bz.y);
                    float n = tanhf(xn.y + r * (gn.y + bn.y));
                    o.y = (1.0f - z) * n + z * hv.y;
                }
                {
                    float r = sigmoidf_(xr.z + gr.z + br.z);
                    float z = sigmoidf_(xz.z + gz.z + bz.z);
                    float n = tanhf(xn.z + r * (gn.z + bn.z));
                    o.z = (1.0f - z) * n + z * hv.z;
                }
                {
                    float r = sigmoidf_(xr.w + gr.w + br.w);
                    float z = sigmoidf_(xz.w + gz.w + bz.w);
                    float n = tanhf(xn.w + r * (gn.w + bn.w));
                    o.w = (1.0f - z) * n + z * hv.w;
                }
                *(float4*)&g_out[ob + q * 4] = o;
            }
        }

        if (t < S_ - 1) grid_sync(GRU_CTAS, gen);
    }
}

// =====================================================================
// Kernel 3: per-batch attention (R row-sums computed in-kernel)
// =====================================================================
__global__ void attn_kernel(const float* __restrict__ reps,
                            const int*   __restrict__ counts,
                            const int*   __restrict__ users,
                            const float* __restrict__ Wa,
                            const float* __restrict__ ba,
                            const float* __restrict__ Ws,
                            const float* __restrict__ bs,
                            float*       __restrict__ outp) {
    __shared__ float As[128][KC + 4];
    __shared__ float Bs[64][KC + 4];
    __shared__ float Rs[64];
    __shared__ float scores_s[128];
    __shared__ float wts[S_];
    __shared__ float inv_s;

    const int b   = blockIdx.x;
    const int u   = users[b];
    const int cnt = counts[b];
    const size_t ub = (size_t)u * 512;
    const float* WaU = Wa + (size_t)u * 512 * 512;

    const int tid  = threadIdx.x;
    const int lane = tid & 31;
    const int w    = tid >> 5;
    const int g    = lane >> 2;
    const int t4   = lane & 3;
    const int wm = w * 16;
    const int s0 = wm + g, s1 = wm + g + 8;
    const bool m0q = (s0 >= cnt), m1q = (s1 >= cnt);

    float pr0 = 0.0f, pr1 = 0.0f;

    for (int ot = 0; ot < 8; ot++) {
        const int o0 = ot * 64;
        float c[8][4];
#pragma unroll
        for (int i = 0; i < 8; i++)
#pragma unroll
            for (int j = 0; j < 4; j++) c[i][j] = 0.0f;

        float rp[2] = {0.0f, 0.0f};

        for (int kc = 0; kc < 512; kc += KC) {
#pragma unroll
            for (int i = 0; i < 4; i++) {        // A: masked GRU output rows
                int lin = tid + i * 256;
                int row = lin >> 3, c4 = (lin & 7) * 4;
                float4 v = make_float4(0.f, 0.f, 0.f, 0.f);
                if (row < S_)
                    v = *(const float4*)&g_out[((size_t)b * S_ + row) * 512 + kc + c4];
                if (row >= cnt) {                // replicate reference's -1e6 quantization
                    v.x = (v.x - 1e6f) + 1e6f; v.y = (v.y - 1e6f) + 1e6f;
                    v.z = (v.z - 1e6f) + 1e6f; v.w = (v.w - 1e6f) + 1e6f;
                }
                As[row][c4 + 0] = v.x; As[row][c4 + 1] = v.y;
                As[row][c4 + 2] = v.z; As[row][c4 + 3] = v.w;
            }
#pragma unroll
            for (int i = 0; i < 2; i++) {        // B: Wa rows + running row-sum
                int lin = tid + i * 256;
                int row = lin >> 3, c4 = (lin & 7) * 4;
                float4 v = *(const float4*)&WaU[(size_t)(o0 + row) * 512 + kc + c4];
                rp[i] += v.x + v.y + v.z + v.w;
                Bs[row][c4 + 0] = v.x; Bs[row][c4 + 1] = v.y;
                Bs[row][c4 + 2] = v.z; Bs[row][c4 + 3] = v.w;
            }
            __syncthreads();
#pragma unroll
            for (int kk = 0; kk < KC; kk += 8) {
                uint32_t a[4];
                a[0] = fasu(As[wm + g    ][kk + t4]);
                a[1] = fasu(As[wm + g + 8][kk + t4]);
                a[2] = fasu(As[wm + g    ][kk + 4 + t4]);
                a[3] = fasu(As[wm + g + 8][kk + 4 + t4]);
#pragma unroll
                for (int nt = 0; nt < 8; nt++) {
                    uint32_t bfr[2];
                    int nb = nt * 8 + g;
                    bfr[0] = fasu(Bs[nb][kk + t4]);
                    bfr[1] = fasu(Bs[nb][kk + 4 + t4]);
                    mma8(c[nt], a, bfr);
                }
            }
            __syncthreads();
        }

        // finish R row-sums for this o-tile (lanes tid&7 share a row)
#pragma unroll
        for (int i = 0; i < 2; i++) {
            float v = rp[i];
            v += __shfl_xor_sync(0xffffffffu, v, 1);
            v += __shfl_xor_sync(0xffffffffu, v, 2);
            v += __shfl_xor_sync(0xffffffffu, v, 4);
            if ((tid & 7) == 0) Rs[i * 32 + (tid >> 3)] = v;
        }
        __syncthreads();

        // epilogue: e = tanh(acc + bias), accumulate e*Ws into row partials
#pragma unroll
        for (int nt = 0; nt < 8; nt++) {
            int cl  = nt * 8 + 2 * t4;           // local col in o-tile
            int col = o0 + cl;
            float baa = ba[ub + col], bab = ba[ub + col + 1];
            float Ca = baa - 1e6f * Rs[cl];
            float Cb = bab - 1e6f * Rs[cl + 1];
            float wsa = Ws[ub + col], wsb = Ws[ub + col + 1];
            pr0 += tanhf(c[nt][0] + (m0q ? Ca : baa)) * wsa
                 + tanhf(c[nt][1] + (m0q ? Cb : bab)) * wsb;
            pr1 += tanhf(c[nt][2] + (m1q ? Ca : baa)) * wsa
                 + tanhf(c[nt][3] + (m1q ? Cb : bab)) * wsb;
        }
        __syncthreads();
    }

    pr0 += __shfl_xor_sync(0xffffffffu, pr0, 1);
    pr0 += __shfl_xor_sync(0xffffffffu, pr0, 2);
    pr1 += __shfl_xor_sync(0xffffffffu, pr1, 1);
    pr1 += __shfl_xor_sync(0xffffffffu, pr1, 2);
    float bsu = bs[u];
    if (t4 == 0) {
        if (s0 < S_) scores_s[s0] = pr0 + bsu;
        if (s1 < S_) scores_s[s1] = pr1 + bsu;
    }
    __syncthreads();

    if (w == 0) {
        float m = -1e30f;
        for (int s = lane; s < S_; s += 32) m = fmaxf(m, scores_s[s]);
#pragma unroll
        for (int off = 16; off > 0; off >>= 1) m = fmaxf(m, __shfl_xor_sync(0xffffffffu, m, off));
        float sum = 0.0f;
        for (int s = lane; s < S_; s += 32) {
            float e = expf(scores_s[s] - m);
            wts[s] = e;
            sum += e;
        }
#pragma unroll
        for (int off = 16; off > 0; off >>= 1) sum += __shfl_xor_sync(0xffffffffu, sum, off);
        if (lane == 0) inv_s = 1.0f / sum;
    }
    __syncthreads();

    const float* rb = reps + (size_t)b * S_ * 512;
    float acc0 = 0.0f, acc1 = 0.0f;
    for (int s = 0; s < S_; s++) {
        float wv = wts[s];
        acc0 += wv * rb[(size_t)s * 512 + tid];
        acc1 += wv * rb[(size_t)s * 512 + 256 + tid];
    }
    float inv = inv_s;
    outp[(size_t)b * 512 + tid]       = acc0 * inv;
    outp[(size_t)b * 512 + 256 + tid] = acc1 * inv;
}

// =====================================================================
extern "C" void kernel_launch(void* const* d_in, const int* in_sizes, int n_in,
                              void* d_out, int out_size) {
    (void)in_sizes; (void)n_in; (void)out_size;
    const float* reps   = (const float*)d_in[0];
    const float* hidden = (const float*)d_in[1];
    const int*   counts = (const int*)  d_in[2];
    const int*   users  = (const int*)  d_in[3];
    const float* Wih    = (const float*)d_in[4];
    const float* Whh    = (const float*)d_in[5];
    const float* bih    = (const float*)d_in[6];
    const float* bhh    = (const float*)d_in[7];
    const float* Wa     = (const float*)d_in[8];
    const float* ba     = (const float*)d_in[9];
    const float* Wsc    = (const float*)d_in[10];
    const float* bsc    = (const float*)d_in[11];
    float* outp = (float*)d_out;

    const int SMEM_PIPE = STAGE_F * 2 * 4;   // 73728 bytes
    cudaFuncSetAttribute(xproj_kernel, cudaFuncAttributeMaxDynamicSharedMemorySize, SMEM_PIPE);
    cudaFuncSetAttribute(gru_persist_kernel, cudaFuncAttributeMaxDynamicSharedMemorySize, SMEM_PIPE);

    xproj_kernel<<<dim3(800, 12), 256, SMEM_PIPE>>>(reps, Wih, bih);
    gru_persist_kernel<<<GRU_CTAS, 256, SMEM_PIPE>>>(hidden, Whh, bhh);
    attn_kernel<<<B_, 256>>>(reps, counts, users, Wa, ba, Wsc, bsc, outp);
}